// round 16
// baseline (speedup 1.0000x reference)
#include <cuda_runtime.h>
#include <cuda_fp16.h>
#include <cstdint>
#include <math.h>

#define NN 50000
#define EE 800000
#define FIN 100
#define FINP 104        // FIN padded to 8-half multiple (16B row alignment)
#define HID 128
#define NH 2
#define C2 256          // NH*HID
#define NOUT 47
#define NEG 0.2f
#define SCAN_BLOCKS 49  // ceil(NN/1024)

// ---------------- scratch (device globals; no allocation allowed) ------------
__device__ __half g_h16[(size_t)NN * C2];     // fp16 h (gather source) / h2
__device__ __half g_agg16[(size_t)NN * C2];   // aggregation output (next GEMM A)
__device__ __half g_x16[(size_t)NN * FINP];   // fp16 padded x
__device__ __half g_w0h[C2 * FINP];
__device__ __half g_w1h[C2 * C2];
__device__ __half g_wp1h[HID * C2];
// two-part attention scores: [n][head][part] -> n*4 + head*2 + part
__device__ float  g_al2[(size_t)NN * 4];
__device__ float  g_ar2[(size_t)NN * 4];
__device__ int    g_deg[NN];                  // zero at entry / re-zeroed by scan1
__device__ int    g_rowstart[NN + 1];
__device__ int    g_cursor[NN];
__device__ int    g_srcsorted[EE];
__device__ int    g_blocksum[SCAN_BLOCKS];

// ---------------- fp32 -> fp16 conversions ------------------------------------
__global__ void k_f2h_x(const float* __restrict__ s, __half* __restrict__ d) {
    int idx = blockIdx.x * blockDim.x + threadIdx.x;
    if (idx >= NN * 13) return;
    int r = idx / 13, c = (idx % 13) * 8;
    const float* src = s + (size_t)r * FIN + c;      // row*400B: 16B-aligned
    __half2 h0, h1, h2, h3;
    if (c <= 92) {
        float4 a = *(const float4*)src;
        float4 b = *(const float4*)(src + 4);
        h0 = __floats2half2_rn(a.x, a.y);
        h1 = __floats2half2_rn(a.z, a.w);
        h2 = __floats2half2_rn(b.x, b.y);
        h3 = __floats2half2_rn(b.z, b.w);
    } else {   // c == 96: 4 valid floats, 4 zero pad
        float4 a = *(const float4*)src;
        h0 = __floats2half2_rn(a.x, a.y);
        h1 = __floats2half2_rn(a.z, a.w);
        h2 = __floats2half2_rn(0.f, 0.f);
        h3 = __floats2half2_rn(0.f, 0.f);
    }
    uint4 o = make_uint4(*(unsigned*)&h0, *(unsigned*)&h1,
                         *(unsigned*)&h2, *(unsigned*)&h3);
    *(uint4*)(d + (size_t)r * FINP + c) = o;
}

__global__ void k_f2h_pad(const float* __restrict__ s, __half* __restrict__ d,
                          int rows, int kin, int kout) {
    int i = blockIdx.x * blockDim.x + threadIdx.x;
    if (i >= rows * kout) return;
    int r = i / kout, c = i % kout;
    d[i] = (c < kin) ? __float2half(s[(size_t)r * kin + c]) : __float2half(0.f);
}

// merged W1 + Wp1 conversion (both dense fp32 -> fp16, vectorized by 4)
__global__ void k_f2h_w1wp1(const float* __restrict__ w1, __half* __restrict__ d1,
                            const float* __restrict__ wp1, __half* __restrict__ d2) {
    const int n1 = C2 * C2 / 4;      // 16384 float4 groups
    const int n2 = HID * C2 / 4;     // 8192
    int g = blockIdx.x * blockDim.x + threadIdx.x;
    const float* s;
    __half* d;
    int idx;
    if (g < n1)      { s = w1;  d = d1; idx = g * 4; }
    else if (g < n1 + n2) { s = wp1; d = d2; idx = (g - n1) * 4; }
    else return;
    float4 v = *(const float4*)(s + idx);
    __half2 h0 = __floats2half2_rn(v.x, v.y);
    __half2 h1 = __floats2half2_rn(v.z, v.w);
    *(uint2*)(d + idx) = make_uint2(*(unsigned*)&h0, *(unsigned*)&h1);
}

// ---------------- CSR build --------------------------------------------------
__global__ void k_deg(const int* __restrict__ ei) {
    int e = blockIdx.x * blockDim.x + threadIdx.x;
    if (e < EE) atomicAdd(&g_deg[ei[EE + e]], 1);
}

__global__ __launch_bounds__(1024) void k_scan1() {
    __shared__ int s[1024];
    int tid = threadIdx.x;
    int i = blockIdx.x * 1024 + tid;
    int v = (i < NN) ? g_deg[i] : 0;
    s[tid] = v;
    __syncthreads();
    #pragma unroll
    for (int o = 1; o < 1024; o <<= 1) {
        int t = (tid >= o) ? s[tid - o] : 0;
        __syncthreads();
        s[tid] += t;
        __syncthreads();
    }
    if (i < NN) {
        g_rowstart[i] = s[tid] - v;
        g_deg[i] = 0;   // reset for next graph replay
    }
    if (tid == 1023) g_blocksum[blockIdx.x] = s[1023];
}

__global__ __launch_bounds__(1024) void k_scan3() {
    __shared__ int myoff;
    int tid = threadIdx.x;
    if (tid == 0) {
        int run = 0, off = 0;
        #pragma unroll 1
        for (int b = 0; b < SCAN_BLOCKS; b++) {
            if (b == (int)blockIdx.x) off = run;
            run += g_blocksum[b];
        }
        myoff = off;
        if (blockIdx.x == 0) g_rowstart[NN] = run;
    }
    __syncthreads();
    int i = blockIdx.x * 1024 + tid;
    if (i < NN) {
        int r = g_rowstart[i] + myoff;
        g_rowstart[i] = r;
        g_cursor[i]   = r;
    }
}

__global__ void k_scatter(const int* __restrict__ ei) {
    int e = blockIdx.x * blockDim.x + threadIdx.x;
    if (e < EE) {
        int s = ei[e];
        int d = ei[EE + e];
        int pos = atomicAdd(&g_cursor[d], 1);
        g_srcsorted[pos] = s;
    }
}

// ---------------- fp16 tensor-core GEMM (cp.async 2-stage pipeline) ----------
__device__ __forceinline__ void cp16(uint32_t dst, const __half* __restrict__ src,
                                     int bytes) {
    asm volatile("cp.async.cg.shared.global [%0], [%1], 16, %2;\n"
                 :: "r"(dst), "l"(src), "r"(bytes));
}

__global__ __launch_bounds__(256, 2) void k_gemm_mma(
    const __half* __restrict__ A, const __half* __restrict__ W,
    const float* __restrict__ bias,
    __half* __restrict__ C16,
    const float* __restrict__ attl, const float* __restrict__ attr,
    int M, int K, int Ncol)
{
    __shared__ __align__(16) __half As[2][128][40];
    __shared__ __align__(16) __half Bs[2][128][40];
    __shared__ __align__(16) float attls[HID];
    __shared__ __align__(16) float attrs[HID];
    const int tid = threadIdx.x;
    const int wid = tid >> 5, lane = tid & 31;
    const int wm = (wid & 3) << 5;
    const int wn = (wid >> 2) << 6;
    const int bm = blockIdx.y * 128, bn = blockIdx.x * 128;
    const int head = bn >> 7;
    const bool has_alpha = (attl != nullptr);

    if (has_alpha && tid < HID) {
        attls[tid] = attl[head * HID + tid];
        attrs[tid] = attr[head * HID + tid];
    }

    float c[2][8][4];
    #pragma unroll
    for (int mt = 0; mt < 2; mt++)
        #pragma unroll
        for (int nt = 0; nt < 8; nt++)
            #pragma unroll
            for (int q = 0; q < 4; q++) c[mt][nt][q] = 0.f;

    const int lrow = tid >> 1;
    const int lk16 = (tid & 1) << 4;
    const int arow = bm + lrow;
    const int wrow = bn + lrow;
    const bool aok = arow < M;
    const bool wok = wrow < Ncol;
    const __half* __restrict__ Ap = A + (size_t)(aok ? arow : 0) * K;
    const __half* __restrict__ Wp = W + (size_t)(wok ? wrow : 0) * K;

    const uint32_t sa0 = (uint32_t)__cvta_generic_to_shared(&As[0][lrow][lk16]);
    const uint32_t sb0 = (uint32_t)__cvta_generic_to_shared(&Bs[0][lrow][lk16]);
    const uint32_t stage_stride = 128 * 40 * 2;

    const int ntiles = (K + 31) >> 5;

    auto issue = [&](int st, int t) {
        int k0 = (t << 5) + lk16;
        int ka0 = aok ? min(max((K - k0) * 2, 0), 16) : 0;
        int ka1 = aok ? min(max((K - k0 - 8) * 2, 0), 16) : 0;
        int kw0 = wok ? min(max((K - k0) * 2, 0), 16) : 0;
        int kw1 = wok ? min(max((K - k0 - 8) * 2, 0), 16) : 0;
        uint32_t da = sa0 + st * stage_stride;
        uint32_t db = sb0 + st * stage_stride;
        cp16(da,      Ap + (ka0 ? k0     : 0), ka0);
        cp16(da + 16, Ap + (ka1 ? k0 + 8 : 0), ka1);
        cp16(db,      Wp + (kw0 ? k0     : 0), kw0);
        cp16(db + 16, Wp + (kw1 ? k0 + 8 : 0), kw1);
        asm volatile("cp.async.commit_group;\n");
    };

    issue(0, 0);

    for (int t = 0; t < ntiles; t++) {
        const int cur = t & 1;
        if (t + 1 < ntiles) {
            issue(cur ^ 1, t + 1);
            asm volatile("cp.async.wait_group 1;\n");
        } else {
            asm volatile("cp.async.wait_group 0;\n");
        }
        __syncthreads();

        #pragma unroll
        for (int kk = 0; kk < 32; kk += 16) {
            unsigned a[2][4];
            #pragma unroll
            for (int mt = 0; mt < 2; mt++) {
                unsigned addr = (unsigned)__cvta_generic_to_shared(
                    &As[cur][wm + (mt << 4) + (lane & 15)][kk + ((lane >> 4) << 3)]);
                asm volatile(
                    "ldmatrix.sync.aligned.m8n8.x4.shared.b16 {%0,%1,%2,%3}, [%4];"
                    : "=r"(a[mt][0]), "=r"(a[mt][1]), "=r"(a[mt][2]), "=r"(a[mt][3])
                    : "r"(addr));
            }
            #pragma unroll
            for (int nt = 0; nt < 8; nt++) {
                int brow = wn + (nt << 3) + (lane >> 2);
                int bcol = kk + ((lane & 3) << 1);
                unsigned b0 = *(const unsigned*)&Bs[cur][brow][bcol];
                unsigned b1 = *(const unsigned*)&Bs[cur][brow][bcol + 8];
                #pragma unroll
                for (int mt = 0; mt < 2; mt++) {
                    asm volatile(
                        "mma.sync.aligned.m16n8k16.row.col.f32.f16.f16.f32 "
                        "{%0,%1,%2,%3}, {%4,%5,%6,%7}, {%8,%9}, {%0,%1,%2,%3};"
                        : "+f"(c[mt][nt][0]), "+f"(c[mt][nt][1]),
                          "+f"(c[mt][nt][2]), "+f"(c[mt][nt][3])
                        : "r"(a[mt][0]), "r"(a[mt][1]), "r"(a[mt][2]), "r"(a[mt][3]),
                          "r"(b0), "r"(b1));
                }
            }
        }
        __syncthreads();
    }

    const int rbase = bm + wm + (lane >> 2);
    const int cbase = bn + wn + ((lane & 3) << 1);
    const int clocal = wn + ((lane & 3) << 1);
    #pragma unroll
    for (int mt = 0; mt < 2; mt++) {
        #pragma unroll
        for (int hf = 0; hf < 2; hf++) {
            int r = rbase + (mt << 4) + (hf << 3);
            float pl = 0.f, pr = 0.f;
            if (r < M) {
                #pragma unroll
                for (int nt = 0; nt < 8; nt++) {
                    int col = cbase + (nt << 3);
                    float v0 = c[mt][nt][hf * 2 + 0] + bias[col];
                    float v1 = c[mt][nt][hf * 2 + 1] + bias[col + 1];
                    __half2 hv = __floats2half2_rn(v0, v1);
                    *(unsigned*)(C16 + (size_t)r * Ncol + col) = *(unsigned*)&hv;
                    if (has_alpha) {
                        int cl = clocal + (nt << 3);
                        pl += v0 * attls[cl] + v1 * attls[cl + 1];
                        pr += v0 * attrs[cl] + v1 * attrs[cl + 1];
                    }
                }
            }
            if (has_alpha) {
                pl += __shfl_xor_sync(0xffffffffu, pl, 1);
                pl += __shfl_xor_sync(0xffffffffu, pl, 2);
                pr += __shfl_xor_sync(0xffffffffu, pr, 1);
                pr += __shfl_xor_sync(0xffffffffu, pr, 2);
                if ((lane & 3) == 0 && r < M) {
                    int part = wn >> 6;
                    g_al2[(size_t)r * 4 + head * 2 + part] = pl;
                    g_ar2[(size_t)r * 4 + head * 2 + part] = pr;
                }
            }
        }
    }
}

__device__ __forceinline__ float lrelu(float x) { return x > 0.f ? x : NEG * x; }

__device__ __forceinline__ void fma8_h(float* acc, float w, uint4 u) {
    float2 f0 = __half22float2(*(__half2*)&u.x);
    float2 f1 = __half22float2(*(__half2*)&u.y);
    float2 f2 = __half22float2(*(__half2*)&u.z);
    float2 f3 = __half22float2(*(__half2*)&u.w);
    acc[0] += w * f0.x; acc[1] += w * f0.y;
    acc[2] += w * f1.x; acc[3] += w * f1.y;
    acc[4] += w * f2.x; acc[5] += w * f2.y;
    acc[6] += w * f3.x; acc[7] += w * f3.y;
}

// ---------------- GAT aggregation: one warp per dst, BOTH heads --------------
__global__ __launch_bounds__(256) void k_aggregate(
    const __half* __restrict__ h16, __half* __restrict__ out)
{
    int d = (blockIdx.x * blockDim.x + threadIdx.x) >> 5;
    int lane = threadIdx.x & 31;
    if (d >= NN) return;
    int start = g_rowstart[d];
    int end   = g_rowstart[d + 1];
    float4 arp = *(const float4*)&g_ar2[(size_t)d * 4];
    const bool h0sel = lane < 16;
    float arm = h0sel ? (arp.x + arp.y) : (arp.z + arp.w);

    const __half* __restrict__ hb = h16 + lane * 8;
    float acc[8] = {0.f, 0.f, 0.f, 0.f, 0.f, 0.f, 0.f, 0.f};
    float den = 0.f;

    int i = start;
    for (; i + 4 <= end; i += 4) {
        int s0 = g_srcsorted[i + 0];
        int s1 = g_srcsorted[i + 1];
        int s2 = g_srcsorted[i + 2];
        int s3 = g_srcsorted[i + 3];
        float4 A0 = *(const float4*)&g_al2[(size_t)s0 * 4];
        float4 A1 = *(const float4*)&g_al2[(size_t)s1 * 4];
        float4 A2 = *(const float4*)&g_al2[(size_t)s2 * 4];
        float4 A3 = *(const float4*)&g_al2[(size_t)s3 * 4];
        uint4 u0 = *(const uint4*)(hb + (size_t)s0 * C2);
        uint4 u1 = *(const uint4*)(hb + (size_t)s1 * C2);
        uint4 u2 = *(const uint4*)(hb + (size_t)s2 * C2);
        uint4 u3 = *(const uint4*)(hb + (size_t)s3 * C2);
        float a0 = h0sel ? (A0.x + A0.y) : (A0.z + A0.w);
        float a1 = h0sel ? (A1.x + A1.y) : (A1.z + A1.w);
        float a2 = h0sel ? (A2.x + A2.y) : (A2.z + A2.w);
        float a3 = h0sel ? (A3.x + A3.y) : (A3.z + A3.w);
        float w0 = __expf(lrelu(a0 + arm));
        float w1 = __expf(lrelu(a1 + arm));
        float w2 = __expf(lrelu(a2 + arm));
        float w3 = __expf(lrelu(a3 + arm));
        den += (w0 + w1) + (w2 + w3);
        fma8_h(acc, w0, u0);
        fma8_h(acc, w1, u1);
        fma8_h(acc, w2, u2);
        fma8_h(acc, w3, u3);
    }
    for (; i < end; i++) {
        int s = g_srcsorted[i];
        float4 A = *(const float4*)&g_al2[(size_t)s * 4];
        uint4 u = *(const uint4*)(hb + (size_t)s * C2);
        float a = h0sel ? (A.x + A.y) : (A.z + A.w);
        float w = __expf(lrelu(a + arm));
        den += w;
        fma8_h(acc, w, u);
    }

    float inv = den > 0.f ? 1.f / den : 0.f;
    union { uint4 u; __half h[8]; } ov;
    #pragma unroll
    for (int j = 0; j < 8; j++)
        ov.h[j] = __float2half(fmaxf(acc[j] * inv, 0.f));
    *(uint4*)(out + (size_t)d * C2 + lane * 8) = ov.u;
}

// ---------------- final: fp16 h2, Wp2 staged in smem, warp per node -----------
__global__ __launch_bounds__(256) void k_final(
    const __half* __restrict__ h2, const float* __restrict__ Wp2,
    const float* __restrict__ bp2, float* __restrict__ out)
{
    __shared__ __align__(16) float xs[8][132];     // 528B rows (16x)
    __shared__ __align__(16) float wp2s[NOUT * 133];
    __shared__ __align__(16) float bp2s[48];
    int tid = threadIdx.x, w = tid >> 5, lane = tid & 31;
    for (int i = tid; i < NOUT * HID; i += 256) {
        int r = i >> 7, c = i & 127;
        wp2s[r * 133 + c] = Wp2[i];
    }
    if (tid < NOUT) bp2s[tid] = bp2[tid];
    __syncthreads();

    int base = blockIdx.x * 128 + w * 16;
    const float* wrA = &wp2s[(lane < NOUT ? lane : 0) * 133];
    const float* wrB = &wp2s[(lane < NOUT - 32 ? lane + 32 : 0) * 133];
    #pragma unroll 1
    for (int it = 0; it < 16; it++) {
        int n = base + it;
        if (n >= NN) break;
        uint2 hv = ((const uint2*)(h2 + (size_t)n * HID))[lane];
        float2 f0 = __half22float2(*(__half2*)&hv.x);
        float2 f1 = __half22float2(*(__half2*)&hv.y);
        *(float4*)&xs[w][lane * 4] = make_float4(f0.x, f0.y, f1.x, f1.y);
        __syncwarp();
        float sA0 = 0.f, sA1 = 0.f, sA2 = 0.f, sA3 = 0.f;
        float sB0 = 0.f, sB1 = 0.f, sB2 = 0.f, sB3 = 0.f;
        #pragma unroll
        for (int k = 0; k < HID; k += 4) {
            float x0 = xs[w][k], x1 = xs[w][k + 1];
            float x2 = xs[w][k + 2], x3 = xs[w][k + 3];
            sA0 += wrA[k] * x0;     sA1 += wrA[k + 1] * x1;
            sA2 += wrA[k + 2] * x2; sA3 += wrA[k + 3] * x3;
            sB0 += wrB[k] * x0;     sB1 += wrB[k + 1] * x1;
            sB2 += wrB[k + 2] * x2; sB3 += wrB[k + 3] * x3;
        }
        float lgA = (lane < NOUT) ?
            (sA0 + sA1) + (sA2 + sA3) + bp2s[lane] : -1e30f;
        float lgB = (lane < NOUT - 32) ?
            (sB0 + sB1) + (sB2 + sB3) + bp2s[lane + 32] : -1e30f;
        float m = fmaxf(lgA, lgB);
        #pragma unroll
        for (int o = 16; o; o >>= 1)
            m = fmaxf(m, __shfl_xor_sync(0xffffffffu, m, o));
        float e = ((lane < NOUT) ? __expf(lgA - m) : 0.f) +
                  ((lane < NOUT - 32) ? __expf(lgB - m) : 0.f);
        #pragma unroll
        for (int o = 16; o; o >>= 1)
            e += __shfl_xor_sync(0xffffffffu, e, o);
        float lz = m + __logf(e);
        if (lane < NOUT) out[(size_t)n * NOUT + lane] = lgA - lz;
        if (lane < NOUT - 32) out[(size_t)n * NOUT + 32 + lane] = lgB - lz;
        __syncwarp();
    }
}

// ---------------- launch ------------------------------------------------------
extern "C" void kernel_launch(void* const* d_in, const int* in_sizes, int n_in,
                              void* d_out, int out_size)
{
    const float* x     = (const float*)d_in[0];
    const int*   ei    = (const int*)  d_in[1];
    const float* W0    = (const float*)d_in[2];
    const float* b0    = (const float*)d_in[3];
    const float* attl0 = (const float*)d_in[4];
    const float* attr0 = (const float*)d_in[5];
    const float* W1    = (const float*)d_in[6];
    const float* b1    = (const float*)d_in[7];
    const float* attl1 = (const float*)d_in[8];
    const float* attr1 = (const float*)d_in[9];
    const float* Wp1   = (const float*)d_in[10];
    const float* bp1   = (const float*)d_in[11];
    const float* Wp2   = (const float*)d_in[12];
    const float* bp2   = (const float*)d_in[13];
    float* out = (float*)d_out;

    __half *ph16 = nullptr, *pagg = nullptr, *px16 = nullptr;
    __half *pw0 = nullptr, *pw1 = nullptr, *pwp1 = nullptr;
    cudaGetSymbolAddress((void**)&ph16, g_h16);
    cudaGetSymbolAddress((void**)&pagg, g_agg16);
    cudaGetSymbolAddress((void**)&px16, g_x16);
    cudaGetSymbolAddress((void**)&pw0,  g_w0h);
    cudaGetSymbolAddress((void**)&pw1,  g_w1h);
    cudaGetSymbolAddress((void**)&pwp1, g_wp1h);

    dim3 g256(C2 / 128, (NN + 127) / 128);   // (2, 391)
    dim3 g128(HID / 128, (NN + 127) / 128);  // (1, 391)
    int agg_blocks = (NN * 32 + 255) / 256;  // 6250

    // ONE side stream (the configuration proven safe in R12/R14) + events.
    cudaStream_t s1;
    cudaEvent_t e_fork, e_csr, e_side;
    cudaStreamCreateWithFlags(&s1, cudaStreamNonBlocking);
    cudaEventCreateWithFlags(&e_fork, cudaEventDisableTiming);
    cudaEventCreateWithFlags(&e_csr,  cudaEventDisableTiming);
    cudaEventCreateWithFlags(&e_side, cudaEventDisableTiming);

    cudaEventRecord(e_fork, 0);
    cudaStreamWaitEvent(s1, e_fork, 0);

    // s1: CSR chain first (e_csr lets agg0 start without waiting for the
    // weight conversions), then W1+Wp1 conversion (e_side gates gemm1).
    k_deg<<<(EE + 255) / 256, 256, 0, s1>>>(ei);
    k_scan1<<<SCAN_BLOCKS, 1024, 0, s1>>>();
    k_scan3<<<SCAN_BLOCKS, 1024, 0, s1>>>();
    k_scatter<<<(EE + 255) / 256, 256, 0, s1>>>(ei);
    cudaEventRecord(e_csr, s1);
    {
        int total = C2 * C2 / 4 + HID * C2 / 4;
        k_f2h_w1wp1<<<(total + 255) / 256, 256, 0, s1>>>(W1, pw1, Wp1, pwp1);
    }
    cudaEventRecord(e_side, s1);

    // main (legacy) stream: x/W0 conversions, gemm0 (+alpha epilogue)
    k_f2h_x<<<(NN * 13 + 255) / 256, 256>>>(x, px16);
    k_f2h_pad<<<(C2 * FINP + 255) / 256, 256>>>(W0, pw0, C2, FIN, FINP);
    k_gemm_mma<<<g256, 256>>>(px16, pw0, b0, ph16, attl0, attr0,
                              NN, FINP, C2);

    // join CSR -> aggregation
    cudaStreamWaitEvent(0, e_csr, 0);
    k_aggregate<<<agg_blocks, 256>>>(ph16, pagg);

    // join weight conversions -> gemm1
    cudaStreamWaitEvent(0, e_side, 0);
    k_gemm_mma<<<g256, 256>>>(pagg, pw1, b1, ph16, attl1, attr1,
                              NN, C2, C2);
    k_aggregate<<<agg_blocks, 256>>>(ph16, pagg);

    // post-mp GEMM (fp16 h2 into g_h16) + final
    k_gemm_mma<<<g128, 256>>>(pagg, pwp1, bp1, ph16, nullptr, nullptr,
                              NN, C2, HID);
    k_final<<<(NN + 127) / 128, 256>>>(ph16, Wp2, bp2, out);
}

// round 17
// speedup vs baseline: 1.0276x; 1.0276x over previous
#include <cuda_runtime.h>
#include <cuda_fp16.h>
#include <cstdint>
#include <math.h>

#define NN 50000
#define EE 800000
#define FIN 100
#define FINP 104        // FIN padded to 8-half multiple (16B row alignment)
#define HID 128
#define NH 2
#define C2 256          // NH*HID
#define NOUT 47
#define NEG 0.2f
#define SCAN_BLOCKS 49  // ceil(NN/1024)

// ---------------- scratch (device globals; no allocation allowed) ------------
__device__ __half g_h16[(size_t)NN * C2];     // fp16 h (gather source) / h2
__device__ __half g_agg16[(size_t)NN * C2];   // aggregation output (next GEMM A)
__device__ __half g_x16[(size_t)NN * FINP];   // fp16 padded x
__device__ __half g_w0h[C2 * FINP];
__device__ __half g_w1h[C2 * C2];
__device__ __half g_wp1h[HID * C2];
// two-part attention scores: [n][head][part] -> n*4 + head*2 + part
__device__ float  g_al2[(size_t)NN * 4];
__device__ float  g_ar2[(size_t)NN * 4];
__device__ int    g_deg[NN];                  // zero at entry / re-zeroed by scan1
__device__ int    g_rowstart[NN + 1];
__device__ int    g_cursor[NN];
__device__ int    g_srcsorted[EE];
__device__ int    g_blocksum[SCAN_BLOCKS];

// ---------------- fp32 -> fp16 conversions ------------------------------------
// merged x + W0 conversion: both have 100-float rows padded to 104 halves.
__global__ void k_f2h_xw0(const float* __restrict__ x, __half* __restrict__ dx,
                          const float* __restrict__ w0, __half* __restrict__ dw0) {
    const int nx = NN * 13;
    const int nw = C2 * 13;
    int idx = blockIdx.x * blockDim.x + threadIdx.x;
    if (idx >= nx + nw) return;
    const float* s;
    __half* d;
    int r, c;
    if (idx < nx) { r = idx / 13; c = (idx % 13) * 8; s = x;  d = dx; }
    else { int j = idx - nx; r = j / 13; c = (j % 13) * 8; s = w0; d = dw0; }
    const float* src = s + (size_t)r * FIN + c;      // row*400B: 16B-aligned
    __half2 h0, h1, h2, h3;
    if (c <= 92) {
        float4 a = *(const float4*)src;
        float4 b = *(const float4*)(src + 4);
        h0 = __floats2half2_rn(a.x, a.y);
        h1 = __floats2half2_rn(a.z, a.w);
        h2 = __floats2half2_rn(b.x, b.y);
        h3 = __floats2half2_rn(b.z, b.w);
    } else {   // c == 96: 4 valid floats, 4 zero pad
        float4 a = *(const float4*)src;
        h0 = __floats2half2_rn(a.x, a.y);
        h1 = __floats2half2_rn(a.z, a.w);
        h2 = __floats2half2_rn(0.f, 0.f);
        h3 = __floats2half2_rn(0.f, 0.f);
    }
    uint4 o = make_uint4(*(unsigned*)&h0, *(unsigned*)&h1,
                         *(unsigned*)&h2, *(unsigned*)&h3);
    *(uint4*)(d + (size_t)r * FINP + c) = o;
}

// merged W1 + Wp1 conversion (both dense fp32 -> fp16, vectorized by 4)
__global__ void k_f2h_w1wp1(const float* __restrict__ w1, __half* __restrict__ d1,
                            const float* __restrict__ wp1, __half* __restrict__ d2) {
    const int n1 = C2 * C2 / 4;      // 16384 float4 groups
    const int n2 = HID * C2 / 4;     // 8192
    int g = blockIdx.x * blockDim.x + threadIdx.x;
    const float* s;
    __half* d;
    int idx;
    if (g < n1)      { s = w1;  d = d1; idx = g * 4; }
    else if (g < n1 + n2) { s = wp1; d = d2; idx = (g - n1) * 4; }
    else return;
    float4 v = *(const float4*)(s + idx);
    __half2 h0 = __floats2half2_rn(v.x, v.y);
    __half2 h1 = __floats2half2_rn(v.z, v.w);
    *(uint2*)(d + idx) = make_uint2(*(unsigned*)&h0, *(unsigned*)&h1);
}

// ---------------- CSR build --------------------------------------------------
__global__ void k_deg(const int* __restrict__ ei) {
    int e = blockIdx.x * blockDim.x + threadIdx.x;
    if (e < EE) atomicAdd(&g_deg[ei[EE + e]], 1);
}

__global__ __launch_bounds__(1024) void k_scan1() {
    __shared__ int s[1024];
    int tid = threadIdx.x;
    int i = blockIdx.x * 1024 + tid;
    int v = (i < NN) ? g_deg[i] : 0;
    s[tid] = v;
    __syncthreads();
    #pragma unroll
    for (int o = 1; o < 1024; o <<= 1) {
        int t = (tid >= o) ? s[tid - o] : 0;
        __syncthreads();
        s[tid] += t;
        __syncthreads();
    }
    if (i < NN) {
        g_rowstart[i] = s[tid] - v;
        g_deg[i] = 0;   // reset for next graph replay
    }
    if (tid == 1023) g_blocksum[blockIdx.x] = s[1023];
}

__global__ __launch_bounds__(1024) void k_scan3() {
    __shared__ int myoff;
    int tid = threadIdx.x;
    if (tid == 0) {
        int run = 0, off = 0;
        #pragma unroll 1
        for (int b = 0; b < SCAN_BLOCKS; b++) {
            if (b == (int)blockIdx.x) off = run;
            run += g_blocksum[b];
        }
        myoff = off;
        if (blockIdx.x == 0) g_rowstart[NN] = run;
    }
    __syncthreads();
    int i = blockIdx.x * 1024 + tid;
    if (i < NN) {
        int r = g_rowstart[i] + myoff;
        g_rowstart[i] = r;
        g_cursor[i]   = r;
    }
}

__global__ void k_scatter(const int* __restrict__ ei) {
    int e = blockIdx.x * blockDim.x + threadIdx.x;
    if (e < EE) {
        int s = ei[e];
        int d = ei[EE + e];
        int pos = atomicAdd(&g_cursor[d], 1);
        g_srcsorted[pos] = s;
    }
}

// ---------------- fp16 tensor-core GEMM (cp.async 3-stage pipeline) ----------
__device__ __forceinline__ void cp16(uint32_t dst, const __half* __restrict__ src,
                                     int bytes) {
    asm volatile("cp.async.cg.shared.global [%0], [%1], 16, %2;\n"
                 :: "r"(dst), "l"(src), "r"(bytes));
}

__global__ __launch_bounds__(256, 2) void k_gemm_mma(
    const __half* __restrict__ A, const __half* __restrict__ W,
    const float* __restrict__ bias,
    __half* __restrict__ C16,
    const float* __restrict__ attl, const float* __restrict__ attr,
    int M, int K, int Ncol)
{
    __shared__ __align__(16) __half As[3][128][40];
    __shared__ __align__(16) __half Bs[3][128][40];
    __shared__ __align__(16) float attls[HID];
    __shared__ __align__(16) float attrs[HID];
    const int tid = threadIdx.x;
    const int wid = tid >> 5, lane = tid & 31;
    const int wm = (wid & 3) << 5;
    const int wn = (wid >> 2) << 6;
    const int bm = blockIdx.y * 128, bn = blockIdx.x * 128;
    const int head = bn >> 7;
    const bool has_alpha = (attl != nullptr);

    if (has_alpha && tid < HID) {
        attls[tid] = attl[head * HID + tid];
        attrs[tid] = attr[head * HID + tid];
    }

    float c[2][8][4];
    #pragma unroll
    for (int mt = 0; mt < 2; mt++)
        #pragma unroll
        for (int nt = 0; nt < 8; nt++)
            #pragma unroll
            for (int q = 0; q < 4; q++) c[mt][nt][q] = 0.f;

    const int lrow = tid >> 1;
    const int lk16 = (tid & 1) << 4;
    const int arow = bm + lrow;
    const int wrow = bn + lrow;
    const bool aok = arow < M;
    const bool wok = wrow < Ncol;
    const __half* __restrict__ Ap = A + (size_t)(aok ? arow : 0) * K;
    const __half* __restrict__ Wp = W + (size_t)(wok ? wrow : 0) * K;

    const uint32_t sa0 = (uint32_t)__cvta_generic_to_shared(&As[0][lrow][lk16]);
    const uint32_t sb0 = (uint32_t)__cvta_generic_to_shared(&Bs[0][lrow][lk16]);
    const uint32_t stage_stride = 128 * 40 * 2;   // bytes per stage

    const int ntiles = (K + 31) >> 5;

    auto issue = [&](int st, int t) {
        int k0 = (t << 5) + lk16;
        int ka0 = aok ? min(max((K - k0) * 2, 0), 16) : 0;
        int ka1 = aok ? min(max((K - k0 - 8) * 2, 0), 16) : 0;
        int kw0 = wok ? min(max((K - k0) * 2, 0), 16) : 0;
        int kw1 = wok ? min(max((K - k0 - 8) * 2, 0), 16) : 0;
        uint32_t da = sa0 + st * stage_stride;
        uint32_t db = sb0 + st * stage_stride;
        cp16(da,      Ap + (ka0 ? k0     : 0), ka0);
        cp16(da + 16, Ap + (ka1 ? k0 + 8 : 0), ka1);
        cp16(db,      Wp + (kw0 ? k0     : 0), kw0);
        cp16(db + 16, Wp + (kw1 ? k0 + 8 : 0), kw1);
        asm volatile("cp.async.commit_group;\n");
    };

    issue(0, 0);
    if (ntiles > 1) issue(1, 1);

    for (int t = 0; t < ntiles; t++) {
        const int cur = t % 3;
        if (t + 1 < ntiles) {
            asm volatile("cp.async.wait_group 1;\n");
        } else {
            asm volatile("cp.async.wait_group 0;\n");
        }
        __syncthreads();
        if (t + 2 < ntiles)
            issue((t + 2) % 3, t + 2);   // buffer free: compute(t-1) is done

        #pragma unroll
        for (int kk = 0; kk < 32; kk += 16) {
            unsigned a[2][4];
            #pragma unroll
            for (int mt = 0; mt < 2; mt++) {
                unsigned addr = (unsigned)__cvta_generic_to_shared(
                    &As[cur][wm + (mt << 4) + (lane & 15)][kk + ((lane >> 4) << 3)]);
                asm volatile(
                    "ldmatrix.sync.aligned.m8n8.x4.shared.b16 {%0,%1,%2,%3}, [%4];"
                    : "=r"(a[mt][0]), "=r"(a[mt][1]), "=r"(a[mt][2]), "=r"(a[mt][3])
                    : "r"(addr));
            }
            #pragma unroll
            for (int nt = 0; nt < 8; nt++) {
                int brow = wn + (nt << 3) + (lane >> 2);
                int bcol = kk + ((lane & 3) << 1);
                unsigned b0 = *(const unsigned*)&Bs[cur][brow][bcol];
                unsigned b1 = *(const unsigned*)&Bs[cur][brow][bcol + 8];
                #pragma unroll
                for (int mt = 0; mt < 2; mt++) {
                    asm volatile(
                        "mma.sync.aligned.m16n8k16.row.col.f32.f16.f16.f32 "
                        "{%0,%1,%2,%3}, {%4,%5,%6,%7}, {%8,%9}, {%0,%1,%2,%3};"
                        : "+f"(c[mt][nt][0]), "+f"(c[mt][nt][1]),
                          "+f"(c[mt][nt][2]), "+f"(c[mt][nt][3])
                        : "r"(a[mt][0]), "r"(a[mt][1]), "r"(a[mt][2]), "r"(a[mt][3]),
                          "r"(b0), "r"(b1));
                }
            }
        }
        __syncthreads();   // protect buf 'cur' before refill at t+3
    }

    const int rbase = bm + wm + (lane >> 2);
    const int cbase = bn + wn + ((lane & 3) << 1);
    const int clocal = wn + ((lane & 3) << 1);
    #pragma unroll
    for (int mt = 0; mt < 2; mt++) {
        #pragma unroll
        for (int hf = 0; hf < 2; hf++) {
            int r = rbase + (mt << 4) + (hf << 3);
            float pl = 0.f, pr = 0.f;
            if (r < M) {
                #pragma unroll
                for (int nt = 0; nt < 8; nt++) {
                    int col = cbase + (nt << 3);
                    float v0 = c[mt][nt][hf * 2 + 0] + bias[col];
                    float v1 = c[mt][nt][hf * 2 + 1] + bias[col + 1];
                    __half2 hv = __floats2half2_rn(v0, v1);
                    *(unsigned*)(C16 + (size_t)r * Ncol + col) = *(unsigned*)&hv;
                    if (has_alpha) {
                        int cl = clocal + (nt << 3);
                        pl += v0 * attls[cl] + v1 * attls[cl + 1];
                        pr += v0 * attrs[cl] + v1 * attrs[cl + 1];
                    }
                }
            }
            if (has_alpha) {
                pl += __shfl_xor_sync(0xffffffffu, pl, 1);
                pl += __shfl_xor_sync(0xffffffffu, pl, 2);
                pr += __shfl_xor_sync(0xffffffffu, pr, 1);
                pr += __shfl_xor_sync(0xffffffffu, pr, 2);
                if ((lane & 3) == 0 && r < M) {
                    int part = wn >> 6;
                    g_al2[(size_t)r * 4 + head * 2 + part] = pl;
                    g_ar2[(size_t)r * 4 + head * 2 + part] = pr;
                }
            }
        }
    }
}

__device__ __forceinline__ float lrelu(float x) { return x > 0.f ? x : NEG * x; }

__device__ __forceinline__ void fma8_h(float* acc, float w, uint4 u) {
    float2 f0 = __half22float2(*(__half2*)&u.x);
    float2 f1 = __half22float2(*(__half2*)&u.y);
    float2 f2 = __half22float2(*(__half2*)&u.z);
    float2 f3 = __half22float2(*(__half2*)&u.w);
    acc[0] += w * f0.x; acc[1] += w * f0.y;
    acc[2] += w * f1.x; acc[3] += w * f1.y;
    acc[4] += w * f2.x; acc[5] += w * f2.y;
    acc[6] += w * f3.x; acc[7] += w * f3.y;
}

// ---------------- GAT aggregation: one warp per dst, BOTH heads --------------
__global__ __launch_bounds__(256) void k_aggregate(
    const __half* __restrict__ h16, __half* __restrict__ out)
{
    int d = (blockIdx.x * blockDim.x + threadIdx.x) >> 5;
    int lane = threadIdx.x & 31;
    if (d >= NN) return;
    int start = g_rowstart[d];
    int end   = g_rowstart[d + 1];
    float4 arp = *(const float4*)&g_ar2[(size_t)d * 4];
    const bool h0sel = lane < 16;
    float arm = h0sel ? (arp.x + arp.y) : (arp.z + arp.w);

    const __half* __restrict__ hb = h16 + lane * 8;
    float acc[8] = {0.f, 0.f, 0.f, 0.f, 0.f, 0.f, 0.f, 0.f};
    float den = 0.f;

    int i = start;
    for (; i + 4 <= end; i += 4) {
        int s0 = g_srcsorted[i + 0];
        int s1 = g_srcsorted[i + 1];
        int s2 = g_srcsorted[i + 2];
        int s3 = g_srcsorted[i + 3];
        float4 A0 = *(const float4*)&g_al2[(size_t)s0 * 4];
        float4 A1 = *(const float4*)&g_al2[(size_t)s1 * 4];
        float4 A2 = *(const float4*)&g_al2[(size_t)s2 * 4];
        float4 A3 = *(const float4*)&g_al2[(size_t)s3 * 4];
        uint4 u0 = *(const uint4*)(hb + (size_t)s0 * C2);
        uint4 u1 = *(const uint4*)(hb + (size_t)s1 * C2);
        uint4 u2 = *(const uint4*)(hb + (size_t)s2 * C2);
        uint4 u3 = *(const uint4*)(hb + (size_t)s3 * C2);
        float a0 = h0sel ? (A0.x + A0.y) : (A0.z + A0.w);
        float a1 = h0sel ? (A1.x + A1.y) : (A1.z + A1.w);
        float a2 = h0sel ? (A2.x + A2.y) : (A2.z + A2.w);
        float a3 = h0sel ? (A3.x + A3.y) : (A3.z + A3.w);
        float w0 = __expf(lrelu(a0 + arm));
        float w1 = __expf(lrelu(a1 + arm));
        float w2 = __expf(lrelu(a2 + arm));
        float w3 = __expf(lrelu(a3 + arm));
        den += (w0 + w1) + (w2 + w3);
        fma8_h(acc, w0, u0);
        fma8_h(acc, w1, u1);
        fma8_h(acc, w2, u2);
        fma8_h(acc, w3, u3);
    }
    for (; i < end; i++) {
        int s = g_srcsorted[i];
        float4 A = *(const float4*)&g_al2[(size_t)s * 4];
        uint4 u = *(const uint4*)(hb + (size_t)s * C2);
        float a = h0sel ? (A.x + A.y) : (A.z + A.w);
        float w = __expf(lrelu(a + arm));
        den += w;
        fma8_h(acc, w, u);
    }

    float inv = den > 0.f ? 1.f / den : 0.f;
    union { uint4 u; __half h[8]; } ov;
    #pragma unroll
    for (int j = 0; j < 8; j++)
        ov.h[j] = __float2half(fmaxf(acc[j] * inv, 0.f));
    *(uint4*)(out + (size_t)d * C2 + lane * 8) = ov.u;
}

// ---------------- final: fp16 h2, Wp2 staged in smem, warp per node -----------
__global__ __launch_bounds__(256) void k_final(
    const __half* __restrict__ h2, const float* __restrict__ Wp2,
    const float* __restrict__ bp2, float* __restrict__ out)
{
    __shared__ __align__(16) float xs[8][132];     // 528B rows (16x)
    __shared__ __align__(16) float wp2s[NOUT * 133];
    __shared__ __align__(16) float bp2s[48];
    int tid = threadIdx.x, w = tid >> 5, lane = tid & 31;
    for (int i = tid; i < NOUT * HID; i += 256) {
        int r = i >> 7, c = i & 127;
        wp2s[r * 133 + c] = Wp2[i];
    }
    if (tid < NOUT) bp2s[tid] = bp2[tid];
    __syncthreads();

    int base = blockIdx.x * 128 + w * 16;
    const float* wrA = &wp2s[(lane < NOUT ? lane : 0) * 133];
    const float* wrB = &wp2s[(lane < NOUT - 32 ? lane + 32 : 0) * 133];
    #pragma unroll 1
    for (int it = 0; it < 16; it++) {
        int n = base + it;
        if (n >= NN) break;
        uint2 hv = ((const uint2*)(h2 + (size_t)n * HID))[lane];
        float2 f0 = __half22float2(*(__half2*)&hv.x);
        float2 f1 = __half22float2(*(__half2*)&hv.y);
        *(float4*)&xs[w][lane * 4] = make_float4(f0.x, f0.y, f1.x, f1.y);
        __syncwarp();
        float sA0 = 0.f, sA1 = 0.f, sA2 = 0.f, sA3 = 0.f;
        float sB0 = 0.f, sB1 = 0.f, sB2 = 0.f, sB3 = 0.f;
        #pragma unroll
        for (int k = 0; k < HID; k += 4) {
            float x0 = xs[w][k], x1 = xs[w][k + 1];
            float x2 = xs[w][k + 2], x3 = xs[w][k + 3];
            sA0 += wrA[k] * x0;     sA1 += wrA[k + 1] * x1;
            sA2 += wrA[k + 2] * x2; sA3 += wrA[k + 3] * x3;
            sB0 += wrB[k] * x0;     sB1 += wrB[k + 1] * x1;
            sB2 += wrB[k + 2] * x2; sB3 += wrB[k + 3] * x3;
        }
        float lgA = (lane < NOUT) ?
            (sA0 + sA1) + (sA2 + sA3) + bp2s[lane] : -1e30f;
        float lgB = (lane < NOUT - 32) ?
            (sB0 + sB1) + (sB2 + sB3) + bp2s[lane + 32] : -1e30f;
        float m = fmaxf(lgA, lgB);
        #pragma unroll
        for (int o = 16; o; o >>= 1)
            m = fmaxf(m, __shfl_xor_sync(0xffffffffu, m, o));
        float e = ((lane < NOUT) ? __expf(lgA - m) : 0.f) +
                  ((lane < NOUT - 32) ? __expf(lgB - m) : 0.f);
        #pragma unroll
        for (int o = 16; o; o >>= 1)
            e += __shfl_xor_sync(0xffffffffu, e, o);
        float lz = m + __logf(e);
        if (lane < NOUT) out[(size_t)n * NOUT + lane] = lgA - lz;
        if (lane < NOUT - 32) out[(size_t)n * NOUT + 32 + lane] = lgB - lz;
        __syncwarp();
    }
}

// ---------------- launch ------------------------------------------------------
extern "C" void kernel_launch(void* const* d_in, const int* in_sizes, int n_in,
                              void* d_out, int out_size)
{
    const float* x     = (const float*)d_in[0];
    const int*   ei    = (const int*)  d_in[1];
    const float* W0    = (const float*)d_in[2];
    const float* b0    = (const float*)d_in[3];
    const float* attl0 = (const float*)d_in[4];
    const float* attr0 = (const float*)d_in[5];
    const float* W1    = (const float*)d_in[6];
    const float* b1    = (const float*)d_in[7];
    const float* attl1 = (const float*)d_in[8];
    const float* attr1 = (const float*)d_in[9];
    const float* Wp1   = (const float*)d_in[10];
    const float* bp1   = (const float*)d_in[11];
    const float* Wp2   = (const float*)d_in[12];
    const float* bp2   = (const float*)d_in[13];
    float* out = (float*)d_out;

    __half *ph16 = nullptr, *pagg = nullptr, *px16 = nullptr;
    __half *pw0 = nullptr, *pw1 = nullptr, *pwp1 = nullptr;
    cudaGetSymbolAddress((void**)&ph16, g_h16);
    cudaGetSymbolAddress((void**)&pagg, g_agg16);
    cudaGetSymbolAddress((void**)&px16, g_x16);
    cudaGetSymbolAddress((void**)&pw0,  g_w0h);
    cudaGetSymbolAddress((void**)&pw1,  g_w1h);
    cudaGetSymbolAddress((void**)&pwp1, g_wp1h);

    dim3 g256(C2 / 128, (NN + 127) / 128);   // (2, 391)
    dim3 g128(HID / 128, (NN + 127) / 128);  // (1, 391)
    int agg_blocks = (NN * 32 + 255) / 256;  // 6250

    // ONE side stream + events (proven safe in R12/R14/R16).
    cudaStream_t s1;
    cudaEvent_t e_fork, e_csr, e_side;
    cudaStreamCreateWithFlags(&s1, cudaStreamNonBlocking);
    cudaEventCreateWithFlags(&e_fork, cudaEventDisableTiming);
    cudaEventCreateWithFlags(&e_csr,  cudaEventDisableTiming);
    cudaEventCreateWithFlags(&e_side, cudaEventDisableTiming);

    cudaEventRecord(e_fork, 0);
    cudaStreamWaitEvent(s1, e_fork, 0);

    // s1: CSR chain (e_csr gates agg0), then W1+Wp1 conversion (e_side gates gemm1)
    k_deg<<<(EE + 255) / 256, 256, 0, s1>>>(ei);
    k_scan1<<<SCAN_BLOCKS, 1024, 0, s1>>>();
    k_scan3<<<SCAN_BLOCKS, 1024, 0, s1>>>();
    k_scatter<<<(EE + 255) / 256, 256, 0, s1>>>(ei);
    cudaEventRecord(e_csr, s1);
    {
        int total = C2 * C2 / 4 + HID * C2 / 4;
        k_f2h_w1wp1<<<(total + 255) / 256, 256, 0, s1>>>(W1, pw1, Wp1, pwp1);
    }
    cudaEventRecord(e_side, s1);

    // main (legacy) stream: merged x+W0 conversion, gemm0 (+alpha epilogue)
    {
        int total = NN * 13 + C2 * 13;
        k_f2h_xw0<<<(total + 255) / 256, 256>>>(x, px16, W0, pw0);
    }
    k_gemm_mma<<<g256, 256>>>(px16, pw0, b0, ph16, attl0, attr0,
                              NN, FINP, C2);

    // join CSR -> aggregation
    cudaStreamWaitEvent(0, e_csr, 0);
    k_aggregate<<<agg_blocks, 256>>>(ph16, pagg);

    // join weight conversions -> gemm1
    cudaStreamWaitEvent(0, e_side, 0);
    k_gemm_mma<<<g256, 256>>>(pagg, pw1, b1, ph16, attl1, attr1,
                              NN, C2, C2);
    k_aggregate<<<agg_blocks, 256>>>(ph16, pagg);

    // post-mp GEMM (fp16 h2 into g_h16) + final
    k_gemm_mma<<<g128, 256>>>(pagg, pwp1, bp1, ph16, nullptr, nullptr,
                              NN, C2, HID);
    k_final<<<(NN + 127) / 128, 256>>>(ph16, Wp2, bp2, out);
}